// round 2
// baseline (speedup 1.0000x reference)
#include <cuda_runtime.h>
#include <cuda_bf16.h>

// Problem constants
#define B_  64
#define C_  256
#define T_  1536
#define H_  512
#define G4_ 2048   // 4*H

typedef unsigned long long u64;

// -------------------- scratch (static device globals; no allocs) -----------
__device__ float d_Xt[(size_t)B_ * T_ * C_];      // x transposed: [(b*T+t)][C]
__device__ float d_G [(size_t)T_ * B_ * G4_];     // gate preacts: [t][b][4H]
__device__ float d_H0[(size_t)T_ * B_ * H_];      // layer0 hidden seq: [t][b][H]
__device__ float d_c [(size_t)B_ * H_];           // cell state

// grid barrier state
__device__ unsigned g_bar_count = 0;
__device__ unsigned g_bar_gen   = 0;

// -------------------- f32x2 helpers (sm_103a packed fp32 FMA) --------------
__device__ __forceinline__ u64 pk2(float lo, float hi)
{
    u64 r;
    asm("mov.b64 %0, {%1, %2};" : "=l"(r) : "f"(lo), "f"(hi));
    return r;
}
__device__ __forceinline__ float2 upk2(u64 v)
{
    float2 f;
    asm("mov.b64 {%0, %1}, %2;" : "=f"(f.x), "=f"(f.y) : "l"(v));
    return f;
}
__device__ __forceinline__ u64 ffma2(u64 a, u64 b, u64 c)
{
    u64 d;
    asm("fma.rn.f32x2 %0, %1, %2, %3;" : "=l"(d) : "l"(a), "l"(b), "l"(c));
    return d;
}

// -------------------- grid barrier (all 128 blocks co-resident) -------------
__device__ __forceinline__ void grid_barrier(unsigned nblocks)
{
    __syncthreads();
    if (threadIdx.x == 0) {
        __threadfence();                              // release
        unsigned gen = *(volatile unsigned*)&g_bar_gen;
        unsigned arrived = atomicAdd(&g_bar_count, 1u);
        if (arrived == nblocks - 1u) {
            atomicExch(&g_bar_count, 0u);
            __threadfence();
            atomicAdd(&g_bar_gen, 1u);
        } else {
            while (*(volatile unsigned*)&g_bar_gen == gen) __nanosleep(64);
        }
        __threadfence();                              // acquire
    }
    __syncthreads();
}

// -------------------- helpers ---------------------------------------------
// x [B][C][T] -> Xt [(b*T+t)][C]
__global__ __launch_bounds__(256) void transpose_x_kernel(
    const float* __restrict__ x, float* __restrict__ Xt)
{
    __shared__ float tile[32][33];
    int b  = blockIdx.z;
    int t0 = blockIdx.x * 32;
    int c0 = blockIdx.y * 32;
    int tx = threadIdx.x;       // 0..31
    int ty = threadIdx.y;       // 0..7
    #pragma unroll
    for (int j = 0; j < 4; j++) {
        int c = c0 + ty + j * 8;
        tile[ty + j * 8][tx] = x[((size_t)b * C_ + c) * T_ + t0 + tx];
    }
    __syncthreads();
    #pragma unroll
    for (int j = 0; j < 4; j++) {
        int t = t0 + ty + j * 8;
        Xt[((size_t)b * T_ + t) * C_ + c0 + tx] = tile[tx][ty + j * 8];
    }
}

// -------------------- input GEMM -------------------------------------------
// Gout = A(MxK) * W(NxK)^T + b1 + b2
// tile 128(M) x 64(N), KC=16, 256 threads, 8x4 micro-tile.
// perm==1: A rows are r=b*T+t, store at G[t][b][n]; perm==0: store at G[r][n].
__global__ __launch_bounds__(256) void igemm_kernel(
    const float* __restrict__ A, int K,
    const float* __restrict__ W,
    const float* __restrict__ b1, const float* __restrict__ b2,
    float* __restrict__ Gout, int perm)
{
    __shared__ float As[16][129];
    __shared__ float Bs[16][65];

    int    tid   = threadIdx.x;
    int    nbase = blockIdx.x * 64;
    size_t mbase = (size_t)blockIdx.y * 128;
    int    tx    = tid & 15;      // n lane
    int    ty    = tid >> 4;      // m lane (0..15)

    float acc[8][4];
    #pragma unroll
    for (int i = 0; i < 8; i++)
        #pragma unroll
        for (int j = 0; j < 4; j++) acc[i][j] = 0.0f;

    for (int kc = 0; kc < K; kc += 16) {
        __syncthreads();
        #pragma unroll
        for (int i = 0; i < 8; i++) {            // 128 x 16 A elements
            int e = tid + i * 256;
            int k = e & 15, m = e >> 4;
            As[k][m] = A[(mbase + m) * K + kc + k];
        }
        #pragma unroll
        for (int i = 0; i < 4; i++) {            // 64 x 16 W elements
            int e = tid + i * 256;
            int k = e & 15, n = e >> 4;
            Bs[k][n] = W[(size_t)(nbase + n) * K + kc + k];
        }
        __syncthreads();
        #pragma unroll
        for (int k = 0; k < 16; k++) {
            float av[8], bv[4];
            #pragma unroll
            for (int i = 0; i < 8; i++) av[i] = As[k][ty + 16 * i];
            #pragma unroll
            for (int j = 0; j < 4; j++) bv[j] = Bs[k][tx + 16 * j];
            #pragma unroll
            for (int i = 0; i < 8; i++)
                #pragma unroll
                for (int j = 0; j < 4; j++) acc[i][j] += av[i] * bv[j];
        }
    }

    #pragma unroll
    for (int i = 0; i < 8; i++) {
        size_t r = mbase + ty + 16 * i;
        size_t orow;
        if (perm) {
            size_t t = r % T_;
            size_t b = r / T_;
            orow = t * (size_t)B_ * G4_ + b * G4_;
        } else {
            orow = r * (size_t)G4_;
        }
        #pragma unroll
        for (int j = 0; j < 4; j++) {
            int n = nbase + tx + 16 * j;
            Gout[orow + n] = acc[i][j] + b1[n] + b2[n];
        }
    }
}

// -------------------- persistent LSTM scan ----------------------------------
// One launch runs all T timesteps for one layer.
// Grid: 128 blocks (4 b-groups x 32 j-groups), 256 threads.
// Block owns cells (16 b) x (16 j), all 4 gates, full K=512.
// SMEM: Ws[512][64] (Whh slice, loaded ONCE) + Hs[512][16] (h_prev, per step)
//       + Gs[2][16][64] (k-half partial gates).
// Threads: ks = tid>>7 (k-half), txb = (tid>>4)&7 (b pair), txg = tid&15 (gc quad).
#define SCAN_BLOCKS 128

__global__ __launch_bounds__(256) void lstm_scan_kernel(
    const float* __restrict__ G,      // [T][B][4H]
    const float* __restrict__ Whh,    // [4H][H]
    float* __restrict__ hseq,         // h(t,b,k) = hseq + t*ts + b*bs + k
    long ts, long bs,
    float* __restrict__ c_state)      // [B][H]
{
    extern __shared__ float sm[];
    float* Ws = sm;                         // [512][64]
    float* Hs = sm + 512 * 64;              // [512][16]
    float* Gs = sm + 512 * 64 + 512 * 16;   // [2][16][64]

    int tid   = threadIdx.x;
    int jg    = blockIdx.x & 31;
    int bg    = blockIdx.x >> 5;
    int jbase = jg * 16;
    int bbase = bg * 16;

    // ---- load Whh slice once: Ws[k][c] = Whh[(c>>4)*H + jbase + (c&15)][k]
    {
        int c   = tid >> 2;                 // 0..63 local gate col
        int kq  = (tid & 3) * 128;          // k chunk base
        int row = (c >> 4) * H_ + jbase + (c & 15);
        const float4* src = (const float4*)(Whh + (size_t)row * H_ + kq);
        #pragma unroll 4
        for (int i = 0; i < 32; i++) {
            float4 v = src[i];
            int k = kq + i * 4;
            Ws[(k + 0) * 64 + c] = v.x;
            Ws[(k + 1) * 64 + c] = v.y;
            Ws[(k + 2) * 64 + c] = v.z;
            Ws[(k + 3) * 64 + c] = v.w;
        }
    }

    int txg  = tid & 15;          // gc quad lane: cols 4*txg .. +3
    int txb  = (tid >> 4) & 7;    // b pair lane: b = 2*txb, 2*txb+1
    int ks   = tid >> 7;          // k half
    int kbeg = ks * 256;

    int cb = tid >> 4;            // cell batch 0..15
    int cj = tid & 15;            // cell j    0..15

    for (int t = 0; t < T_; t++) {
        __syncthreads();
        // ---- stage h_prev into Hs[k][b]
        {
            int b  = tid & 15;
            int kc = (tid >> 4) * 32;
            if (t == 0) {
                #pragma unroll
                for (int i = 0; i < 32; i++) Hs[(kc + i) * 16 + b] = 0.0f;
            } else {
                const float* hp = hseq + (size_t)(t - 1) * ts
                                       + (size_t)(bbase + b) * bs + kc;
                #pragma unroll
                for (int i = 0; i < 32; i += 4) {
                    float4 v = *(const float4*)(hp + i);
                    Hs[(kc + i + 0) * 16 + b] = v.x;
                    Hs[(kc + i + 1) * 16 + b] = v.y;
                    Hs[(kc + i + 2) * 16 + b] = v.z;
                    Hs[(kc + i + 3) * 16 + b] = v.w;
                }
            }
        }
        __syncthreads();

        // ---- GEMM: partial gates over this thread's k half
        u64 a00 = 0, a10 = 0, a01 = 0, a11 = 0;   // (0.f,0.f) bit pattern
        #pragma unroll 8
        for (int k = kbeg; k < kbeg + 256; k++) {
            float4 w = *(const float4*)(Ws + k * 64 + 4 * txg);
            float2 h = *(const float2*)(Hs + k * 16 + 2 * txb);
            u64 w01 = pk2(w.x, w.y);
            u64 w23 = pk2(w.z, w.w);
            u64 h0  = pk2(h.x, h.x);
            u64 h1  = pk2(h.y, h.y);
            a00 = ffma2(w01, h0, a00);
            a10 = ffma2(w23, h0, a10);
            a01 = ffma2(w01, h1, a01);
            a11 = ffma2(w23, h1, a11);
        }
        // ---- stage partials: Gs[ks][b][c]
        {
            float2 p00 = upk2(a00), p10 = upk2(a10);
            float2 p01 = upk2(a01), p11 = upk2(a11);
            float* dst0 = Gs + (ks * 16 + 2 * txb + 0) * 64 + 4 * txg;
            float* dst1 = Gs + (ks * 16 + 2 * txb + 1) * 64 + 4 * txg;
            *(float4*)dst0 = make_float4(p00.x, p00.y, p10.x, p10.y);
            *(float4*)dst1 = make_float4(p01.x, p01.y, p11.x, p11.y);
        }
        __syncthreads();

        // ---- cell update: one cell per thread
        {
            const float* gt = G + (size_t)t * (B_ * G4_)
                                + (size_t)(bbase + cb) * G4_;
            float pi = gt[0 * H_ + jbase + cj] + Gs[cb * 64 +  0 + cj]
                                               + Gs[(16 + cb) * 64 +  0 + cj];
            float pf = gt[1 * H_ + jbase + cj] + Gs[cb * 64 + 16 + cj]
                                               + Gs[(16 + cb) * 64 + 16 + cj];
            float pg = gt[2 * H_ + jbase + cj] + Gs[cb * 64 + 32 + cj]
                                               + Gs[(16 + cb) * 64 + 32 + cj];
            float po = gt[3 * H_ + jbase + cj] + Gs[cb * 64 + 48 + cj]
                                               + Gs[(16 + cb) * 64 + 48 + cj];

            float si = 1.0f / (1.0f + expf(-pi));
            float sf = 1.0f / (1.0f + expf(-pf));
            float tg = tanhf(pg);
            float so = 1.0f / (1.0f + expf(-po));

            size_t ci = (size_t)(bbase + cb) * H_ + jbase + cj;
            float cprev = (t == 0) ? 0.0f : c_state[ci];
            float cc = sf * cprev + si * tg;
            c_state[ci] = cc;
            hseq[(size_t)t * ts + (size_t)(bbase + cb) * bs + jbase + cj]
                = so * tanhf(cc);
        }

        if (t != T_ - 1) grid_barrier(SCAN_BLOCKS);
    }
}

// -------------------- launch ------------------------------------------------
extern "C" void kernel_launch(void* const* d_in, const int* in_sizes, int n_in,
                              void* d_out, int out_size)
{
    const float* x    = (const float*)d_in[0];
    const float* Wih0 = (const float*)d_in[1];
    const float* Whh0 = (const float*)d_in[2];
    const float* bih0 = (const float*)d_in[3];
    const float* bhh0 = (const float*)d_in[4];
    const float* Wih1 = (const float*)d_in[5];
    const float* Whh1 = (const float*)d_in[6];
    const float* bih1 = (const float*)d_in[7];
    const float* bhh1 = (const float*)d_in[8];
    float* out = (float*)d_out;   // [B][T][H]

    float *Xt, *G, *H0, *c;
    cudaGetSymbolAddress((void**)&Xt, d_Xt);
    cudaGetSymbolAddress((void**)&G,  d_G);
    cudaGetSymbolAddress((void**)&H0, d_H0);
    cudaGetSymbolAddress((void**)&c,  d_c);

    const size_t scan_smem = (512 * 64 + 512 * 16 + 2 * 16 * 64) * sizeof(float);
    cudaFuncSetAttribute(lstm_scan_kernel,
                         cudaFuncAttributeMaxDynamicSharedMemorySize,
                         (int)scan_smem);

    // 1. transpose x -> Xt [(b*T+t)][C]
    transpose_x_kernel<<<dim3(T_ / 32, C_ / 32, B_), dim3(32, 8)>>>(x, Xt);

    // 2. layer-0 input gates: G[t][b][4H] = Xt @ Wih0^T + bih0 + bhh0
    igemm_kernel<<<dim3(G4_ / 64, (B_ * T_) / 128), 256>>>(
        Xt, C_, Wih0, bih0, bhh0, G, /*perm=*/1);

    // 3. layer-0 scan (persistent): H0 layout [t][b][h]
    lstm_scan_kernel<<<SCAN_BLOCKS, 256, scan_smem>>>(
        G, Whh0, H0, (long)(B_ * H_), (long)H_, c);

    // 4. layer-1 input gates: G[t][b][4H] = H0 @ Wih1^T + bih1 + bhh1
    igemm_kernel<<<dim3(G4_ / 64, (B_ * T_) / 128), 256>>>(
        H0, H_, Wih1, bih1, bhh1, G, /*perm=*/0);

    // 5. layer-1 scan (persistent): out layout [b][t][h]
    lstm_scan_kernel<<<SCAN_BLOCKS, 256, scan_smem>>>(
        G, Whh1, out, (long)H_, (long)(T_ * H_), c);
}

// round 9
// speedup vs baseline: 1.2983x; 1.2983x over previous
#include <cuda_runtime.h>
#include <cuda_bf16.h>

// Problem constants
#define B_  64
#define C_  256
#define T_  1536
#define H_  512
#define G4_ 2048   // 4*H

typedef unsigned long long u64;

// -------------------- scratch (static device globals; no allocs) -----------
__device__ float d_Xt[(size_t)B_ * T_ * C_];      // x transposed: [(b*T+t)][C]
__device__ float d_G [(size_t)T_ * B_ * G4_];     // gate preacts: [t][b][4H]
__device__ float d_H0[(size_t)T_ * B_ * H_];      // layer0 hidden seq: [t][b][H]

// per-batch-group grid barrier state (4 groups of 32 blocks)
#define SCAN_BG 4
#define SCAN_JG 32
__device__ unsigned g_cnt[SCAN_BG];
__device__ unsigned g_gen[SCAN_BG];

// -------------------- f32x2 helpers (sm_103a packed fp32) -------------------
__device__ __forceinline__ u64 pk2(float lo, float hi)
{
    u64 r;
    asm("mov.b64 %0, {%1, %2};" : "=l"(r) : "f"(lo), "f"(hi));
    return r;
}
__device__ __forceinline__ float2 upk2(u64 v)
{
    float2 f;
    asm("mov.b64 {%0, %1}, %2;" : "=f"(f.x), "=f"(f.y) : "l"(v));
    return f;
}
__device__ __forceinline__ u64 ffma2(u64 a, u64 b, u64 c)
{
    u64 d;
    asm("fma.rn.f32x2 %0, %1, %2, %3;" : "=l"(d) : "l"(a), "l"(b), "l"(c));
    return d;
}
__device__ __forceinline__ u64 fadd2(u64 a, u64 b)
{
    u64 d;
    asm("add.rn.f32x2 %0, %1, %2;" : "=l"(d) : "l"(a), "l"(b));
    return d;
}

// -------------------- per-group grid barrier --------------------------------
__device__ __forceinline__ void bg_barrier(int bg)
{
    __syncthreads();
    if (threadIdx.x == 0) {
        __threadfence();                               // release h writes
        unsigned gen = *(volatile unsigned*)&g_gen[bg];
        if (atomicAdd(&g_cnt[bg], 1u) == SCAN_JG - 1u) {
            *(volatile unsigned*)&g_cnt[bg] = 0u;
            __threadfence();
            atomicAdd(&g_gen[bg], 1u);
        } else {
            while (*(volatile unsigned*)&g_gen[bg] == gen) __nanosleep(32);
        }
        __threadfence();                               // acquire
    }
    __syncthreads();
}

// -------------------- transpose ---------------------------------------------
// x [B][C][T] -> Xt [(b*T+t)][C]
__global__ __launch_bounds__(256) void transpose_x_kernel(
    const float* __restrict__ x, float* __restrict__ Xt)
{
    __shared__ float tile[32][33];
    int b  = blockIdx.z;
    int t0 = blockIdx.x * 32;
    int c0 = blockIdx.y * 32;
    int tx = threadIdx.x;
    int ty = threadIdx.y;
    #pragma unroll
    for (int j = 0; j < 4; j++) {
        int c = c0 + ty + j * 8;
        tile[ty + j * 8][tx] = x[((size_t)b * C_ + c) * T_ + t0 + tx];
    }
    __syncthreads();
    #pragma unroll
    for (int j = 0; j < 4; j++) {
        int t = t0 + ty + j * 8;
        Xt[((size_t)b * T_ + t) * C_ + c0 + tx] = tile[tx][ty + j * 8];
    }
}

// -------------------- input GEMM (FFMA2, 128x128 tile) ----------------------
// Gout = A(MxK) * W(NxK)^T + b1 + b2
// Thread (ng, mg): rows m0..m0+7 (m-pairs via f32x2), cols n = ng + 16*j.
// Bs holds dup-packed (w,w) per float column -> inner loop LDS.64 conflict-free.
// Half-warp lanes have contiguous ng -> epilogue STG.32 coalesces into 64B runs.
// perm==1: A rows r=b*T+t, store at G[t][b][n]; perm==0: store at G[r][n].
__global__ __launch_bounds__(256, 2) void igemm2_kernel(
    const float* __restrict__ A, int K,
    const float* __restrict__ W,
    const float* __restrict__ b1, const float* __restrict__ b2,
    float* __restrict__ Gout, int perm)
{
    __shared__ float As[16][136];   // [k][m], padded
    __shared__ u64   Bs[16][128];   // [k][n] dup-packed (w_n, w_n)

    int    tid   = threadIdx.x;
    int    nbase = blockIdx.x * 128;
    size_t mbase = (size_t)blockIdx.y * 128;
    int    ng = tid & 15, mg = tid >> 4;
    int    m0 = mg * 8;

    float bias[8];
    #pragma unroll
    for (int j = 0; j < 8; j++) {
        int n = nbase + ng + 16 * j;
        bias[j] = b1[n] + b2[n];
    }

    u64 acc[4][8];
    #pragma unroll
    for (int i = 0; i < 4; i++)
        #pragma unroll
        for (int j = 0; j < 8; j++) acc[i][j] = 0ull;

    for (int kc = 0; kc < K; kc += 16) {
        __syncthreads();
        #pragma unroll
        for (int i = 0; i < 2; i++) {               // stage A: 128x16
            int e = tid * 2 + i;
            int m = e >> 2, kq = (e & 3) * 4;
            float4 v = *(const float4*)(A + (mbase + m) * (size_t)K + kc + kq);
            As[kq + 0][m] = v.x; As[kq + 1][m] = v.y;
            As[kq + 2][m] = v.z; As[kq + 3][m] = v.w;
        }
        #pragma unroll
        for (int i = 0; i < 2; i++) {               // stage W dup: 128x16
            int e = tid * 2 + i;
            int n = e >> 2, kq = (e & 3) * 4;
            float4 v = *(const float4*)(W + (size_t)(nbase + n) * K + kc + kq);
            Bs[kq + 0][n] = pk2(v.x, v.x); Bs[kq + 1][n] = pk2(v.y, v.y);
            Bs[kq + 2][n] = pk2(v.z, v.z); Bs[kq + 3][n] = pk2(v.w, v.w);
        }
        __syncthreads();
        #pragma unroll
        for (int k = 0; k < 16; k++) {
            ulonglong2 a01 = *(const ulonglong2*)(&As[k][m0]);
            ulonglong2 a23 = *(const ulonglong2*)(&As[k][m0 + 4]);
            u64 am[4] = {a01.x, a01.y, a23.x, a23.y};
            u64 bn[8];
            #pragma unroll
            for (int j = 0; j < 8; j++) bn[j] = Bs[k][ng + 16 * j];
            #pragma unroll
            for (int mp = 0; mp < 4; mp++)
                #pragma unroll
                for (int j = 0; j < 8; j++)
                    acc[mp][j] = ffma2(am[mp], bn[j], acc[mp][j]);
        }
    }

    #pragma unroll
    for (int mp = 0; mp < 4; mp++) {
        float2 p[8];
        #pragma unroll
        for (int j = 0; j < 8; j++) p[j] = upk2(acc[mp][j]);
        #pragma unroll
        for (int h = 0; h < 2; h++) {
            size_t r = mbase + m0 + 2 * mp + h;
            size_t orow;
            if (perm) {
                size_t t = r % T_;
                size_t b = r / T_;
                orow = t * (size_t)B_ * G4_ + b * G4_;
            } else {
                orow = r * (size_t)G4_;
            }
            #pragma unroll
            for (int j = 0; j < 8; j++) {
                float v = (h ? p[j].y : p[j].x) + bias[j];
                Gout[orow + nbase + ng + 16 * j] = v;
            }
        }
    }
}

// -------------------- persistent LSTM scan ----------------------------------
// 128 blocks = 4 bg x 32 jg; block owns cells (16 b) x (16 j), all gates.
// SMEM: Ws float[512][64] (Whh slice, once), Hs u64[512][16] (h dup-packed,
// per step), Gq u64[512 groups][8 slots] (k-slice partials). 224 KB.
// Thread GEMM role: warp ks owns 64 k; lane (cq,bq) computes col-pairs
// cp = cq + 8*i (i=0..3, scattered -> conflict-free LDS.64) x batches 4bq..+3.
// Partial store slot = ks ^ cq ^ bq: per output group the 8 warps hit 8
// distinct slots (reader sums all 8; order irrelevant) and the 16 half-warp
// store lanes hit 16 distinct bank-pairs -> conflict-free STS.64.
__global__ __launch_bounds__(256) void lstm_scan_kernel(
    const float* __restrict__ G,      // [T][B][4H]
    const float* __restrict__ Whh,    // [4H][H]
    float* __restrict__ hseq,         // h(t,b,k) at t*ts + b*bs + k
    long ts, long bs)
{
    extern __shared__ float sm[];
    float* Ws = sm;                           // 32768 floats
    u64*   Hp = (u64*)(sm + 32768);           // [512][16] (h,h)
    u64*   Gq = (u64*)(sm + 32768 + 16384);   // [512][8]
    const u64* Wp = (const u64*)Ws;           // [512][32] col-pairs

    int tid   = threadIdx.x;
    int jg    = blockIdx.x & 31;
    int bg    = blockIdx.x >> 5;
    int jbase = jg * 16;
    int bbase = bg * 16;

    // ---- load Whh slice once: Ws[k][c] = Whh[(c>>4)*H + jbase + (c&15)][k]
    {
        int c   = tid >> 2;
        int kq  = (tid & 3) * 128;
        int row = (c >> 4) * H_ + jbase + (c & 15);
        const float4* src = (const float4*)(Whh + (size_t)row * H_ + kq);
        #pragma unroll 4
        for (int i = 0; i < 32; i++) {
            float4 v = src[i];
            int k = kq + i * 4;
            Ws[(k + 0) * 64 + c] = v.x;
            Ws[(k + 1) * 64 + c] = v.y;
            Ws[(k + 2) * 64 + c] = v.z;
            Ws[(k + 3) * 64 + c] = v.w;
        }
    }

    // GEMM roles
    int ks   = tid >> 5;            // warp = k-slice 0..7 (64 k each)
    int lane = tid & 31;
    int cq   = lane & 7;            // col-pairs cq + 8*i
    int bq   = lane >> 3;           // batches 4bq .. 4bq+3
    int kbeg = ks * 64;
    int slot = ks ^ cq ^ bq;        // per-thread constant store slot

    // cell role
    int cb = tid >> 4;              // batch 0..15
    int cj = tid & 15;              // j     0..15
    int jp = cj >> 1, hsel = cj & 1;
    float c_reg = 0.0f;

    // staging role
    int sb  = tid & 15;
    int skc = (tid >> 4) * 32;

    for (int t = 0; t < T_; t++) {
        // prefetch gate preacts for this thread's cell
        const float* gt = G + (size_t)t * (B_ * G4_)
                            + (size_t)(bbase + cb) * G4_ + jbase + cj;
        float pre0 = gt[0 * H_], pre1 = gt[1 * H_];
        float pre2 = gt[2 * H_], pre3 = gt[3 * H_];

        if (t != 0) bg_barrier(bg);

        // ---- stage h_prev (dup-packed) into Hp[k][b]
        if (t == 0) {
            #pragma unroll
            for (int i = 0; i < 32; i++)
                Hp[(size_t)(skc + i) * 16 + sb] = 0ull;
        } else {
            const float* hp = hseq + (size_t)(t - 1) * ts
                                   + (size_t)(bbase + sb) * bs + skc;
            #pragma unroll
            for (int i = 0; i < 32; i += 4) {
                float4 v = *(const float4*)(hp + i);
                Hp[(size_t)(skc + i + 0) * 16 + sb] = pk2(v.x, v.x);
                Hp[(size_t)(skc + i + 1) * 16 + sb] = pk2(v.y, v.y);
                Hp[(size_t)(skc + i + 2) * 16 + sb] = pk2(v.z, v.z);
                Hp[(size_t)(skc + i + 3) * 16 + sb] = pk2(v.w, v.w);
            }
        }
        __syncthreads();

        // ---- GEMM over this warp's 64-k slice: 4 col-pairs x 4 batches
        u64 acc[4][4];
        #pragma unroll
        for (int i = 0; i < 4; i++)
            #pragma unroll
            for (int j = 0; j < 4; j++) acc[i][j] = 0ull;

        #pragma unroll 4
        for (int k = kbeg; k < kbeg + 64; k++) {
            u64 w[4];
            #pragma unroll
            for (int i = 0; i < 4; i++)
                w[i] = Wp[(size_t)k * 32 + cq + 8 * i];       // LDS.64 cf
            ulonglong2 h01 = *(const ulonglong2*)(Hp + (size_t)k * 16 + 4 * bq);
            ulonglong2 h23 = *(const ulonglong2*)(Hp + (size_t)k * 16 + 4 * bq + 2);
            u64 h[4] = {h01.x, h01.y, h23.x, h23.y};
            #pragma unroll
            for (int i = 0; i < 4; i++)
                #pragma unroll
                for (int j = 0; j < 4; j++)
                    acc[i][j] = ffma2(w[i], h[j], acc[i][j]);
        }

        // ---- store partials: group (b, cp), permuted slot (conflict-free)
        #pragma unroll
        for (int i = 0; i < 4; i++)
            #pragma unroll
            for (int j = 0; j < 4; j++)
                Gq[((size_t)(4 * bq + j) * 32 + (cq + 8 * i)) * 8 + slot]
                    = acc[i][j];
        __syncthreads();

        // ---- cell update (one cell per thread, c in register)
        {
            float gate[4];
            #pragma unroll
            for (int g = 0; g < 4; g++) {
                int cp = g * 8 + jp;
                const ulonglong2* p =
                    (const ulonglong2*)(Gq + ((size_t)cb * 32 + cp) * 8);
                ulonglong2 q0 = p[0], q1 = p[1], q2 = p[2], q3 = p[3];
                u64 s = fadd2(fadd2(fadd2(q0.x, q0.y), fadd2(q1.x, q1.y)),
                              fadd2(fadd2(q2.x, q2.y), fadd2(q3.x, q3.y)));
                float2 sf = upk2(s);
                gate[g] = (hsel ? sf.y : sf.x);
            }
            float pi = gate[0] + pre0;
            float pf = gate[1] + pre1;
            float pg = gate[2] + pre2;
            float po = gate[3] + pre3;

            float si = __fdividef(1.0f, 1.0f + __expf(-pi));
            float sf = __fdividef(1.0f, 1.0f + __expf(-pf));
            float tg = __fdividef(2.0f, 1.0f + __expf(-2.0f * pg)) - 1.0f;
            float so = __fdividef(1.0f, 1.0f + __expf(-po));

            c_reg = sf * c_reg + si * tg;
            float th = __fdividef(2.0f, 1.0f + __expf(-2.0f * c_reg)) - 1.0f;
            hseq[(size_t)t * ts + (size_t)(bbase + cb) * bs + jbase + cj]
                = so * th;
        }
    }
}

// -------------------- launch ------------------------------------------------
extern "C" void kernel_launch(void* const* d_in, const int* in_sizes, int n_in,
                              void* d_out, int out_size)
{
    const float* x    = (const float*)d_in[0];
    const float* Wih0 = (const float*)d_in[1];
    const float* Whh0 = (const float*)d_in[2];
    const float* bih0 = (const float*)d_in[3];
    const float* bhh0 = (const float*)d_in[4];
    const float* Wih1 = (const float*)d_in[5];
    const float* Whh1 = (const float*)d_in[6];
    const float* bih1 = (const float*)d_in[7];
    const float* bhh1 = (const float*)d_in[8];
    float* out = (float*)d_out;   // [B][T][H]

    float *Xt, *G, *H0;
    cudaGetSymbolAddress((void**)&Xt, d_Xt);
    cudaGetSymbolAddress((void**)&G,  d_G);
    cudaGetSymbolAddress((void**)&H0, d_H0);

    const size_t scan_smem = (32768 + 16384 + 8192) * sizeof(float);  // 224 KB
    cudaFuncSetAttribute(lstm_scan_kernel,
                         cudaFuncAttributeMaxDynamicSharedMemorySize,
                         (int)scan_smem);

    // 1. transpose x -> Xt [(b*T+t)][C]
    transpose_x_kernel<<<dim3(T_ / 32, C_ / 32, B_), dim3(32, 8)>>>(x, Xt);

    // 2. layer-0 input gates: G[t][b][4H] = Xt @ Wih0^T + bih0 + bhh0
    igemm2_kernel<<<dim3(G4_ / 128, (B_ * T_) / 128), 256>>>(
        Xt, C_, Wih0, bih0, bhh0, G, /*perm=*/1);

    // 3. layer-0 scan (persistent): H0 layout [t][b][h]
    lstm_scan_kernel<<<SCAN_BG * SCAN_JG, 256, scan_smem>>>(
        G, Whh0, H0, (long)(B_ * H_), (long)H_);

    // 4. layer-1 input gates: G[t][b][4H] = H0 @ Wih1^T + bih1 + bhh1
    igemm2_kernel<<<dim3(G4_ / 128, (B_ * T_) / 128), 256>>>(
        H0, H_, Wih1, bih1, bhh1, G, /*perm=*/0);

    // 5. layer-1 scan (persistent): out layout [b][t][h]
    lstm_scan_kernel<<<SCAN_BG * SCAN_JG, 256, scan_smem>>>(
        G, Whh1, out, (long)H_, (long)(T_ * H_));
}